// round 7
// baseline (speedup 1.0000x reference)
#include <cuda_runtime.h>
#include <cuda_fp16.h>
#include <cstdint>

#define B_  32
#define O_  256
#define KK  49
#define HW  625
#define WO  25
#define CKK 12544

#define THREADS 256          // 8 warps: 4(M) x 2(N)
#define NGROUP  128          // channel pairs
#define KG      112          // padded K per group (98 real)
#define KSTEPS  7
#define PITCH   120
#define PITCHB  240
#define A_HALF  30720        // 128 * 240
#define A_BUF   61440        // hi + lo
#define B_BUF   38400        // 160 * 240

#define XROWS   14           // 160-wide pixel tile can span 8 out rows + 6
#define XCH     448          // 14 * 32 floats per channel
#define XSTG    434          // 14 * 31 staged floats per channel
#define XBUFB   3584         // 2 ch * 448 floats * 4B

#define SM_A    0            // 2 * 61440
#define SM_B    122880       // 2 * 38400
#define SM_X    199680       // 2 * 3584
#define SM_KM   206848       // 2 * 448
#define SM_XOFF 207744       // 112 ints
#define SM_RTAB 208192       // 160 ints
#define SMEM_DYN 208832

// Precomputed fp16 hi/lo weights (x256): [t][g][half][o 128][k 120]
__device__ __half g_W[2][NGROUP][2][128][PITCH];

__device__ __forceinline__ uint32_t smem_u32(const void* p) {
    uint32_t a;
    asm("{ .reg .u64 t; cvta.to.shared.u64 t, %1; cvt.u32.u64 %0, t; }" : "=r"(a) : "l"(p));
    return a;
}
__device__ __forceinline__ void ldsm4(uint32_t* r, uint32_t addr) {
    asm volatile("ldmatrix.sync.aligned.m8n8.x4.shared.b16 {%0,%1,%2,%3}, [%4];"
                 : "=r"(r[0]), "=r"(r[1]), "=r"(r[2]), "=r"(r[3]) : "r"(addr));
}
__device__ __forceinline__ void mma_f16(float* d, const uint32_t* a, const uint32_t* b) {
    asm volatile("mma.sync.aligned.m16n8k16.row.col.f32.f16.f16.f32 "
                 "{%0,%1,%2,%3}, {%4,%5,%6,%7}, {%8,%9}, {%0,%1,%2,%3};"
                 : "+f"(d[0]), "+f"(d[1]), "+f"(d[2]), "+f"(d[3])
                 : "r"(a[0]), "r"(a[1]), "r"(a[2]), "r"(a[3]), "r"(b[0]), "r"(b[1]));
}
#define CP16(dst, src) \
    asm volatile("cp.async.cg.shared.global [%0], [%1], 16;" :: "r"(dst), "l"(src) : "memory")
#define CP_COMMIT() asm volatile("cp.async.commit_group;" ::: "memory")
#define CP_WAIT0()  asm volatile("cp.async.wait_group 0;" ::: "memory")

__global__ void precompute_w(const float* __restrict__ w) {
    long idx = (long)blockIdx.x * 256 + threadIdx.x;
    int k = idx % KG;
    int o = (idx / KG) & 127;
    int g = (idx / (KG * 128)) & 127;
    int t = (int)(idx / ((long)KG * 128 * NGROUP));
    if (t >= 2) return;
    float v = 0.f;
    if (k < 98) {
        int ci = k / 49, kl = k - ci * 49;
        v = w[(size_t)(t * 128 + o) * CKK + (g * 2 + ci) * KK + kl] * 256.f;
    }
    __half h = __float2half_rn(v);
    g_W[t][g][0][o][k] = h;
    g_W[t][g][1][o][k] = __float2half_rn(v - __half2float(h));
}

__global__ __launch_bounds__(THREADS, 1)
void dwconv_hmma4(const float* __restrict__ x, const float* __restrict__ kern,
                  const float* __restrict__ bias, float* __restrict__ out)
{
    extern __shared__ __align__(128) char smem[];
    const uint32_t sbase = smem_u32(smem);

    const int tid = threadIdx.x, wid = tid >> 5, lid = tid & 31;
    const int mw = wid >> 1, nw = wid & 1;
    const int blk = blockIdx.x;
    const int pt = blk & 3, t = (blk >> 2) & 1, b = blk >> 3;
    const int p0 = pt * 160, o0 = t * 128;
    const int h0 = p0 / WO;

    int* xoffs = (int*)(smem + SM_XOFF);
    int* rtab  = (int*)(smem + SM_RTAB);
    if (tid < KG) {
        int v = 0;
        if (tid < 98) { int ci = tid >= 49, kl = tid - ci * 49;
                        v = ci * XCH + (kl / 7) * 32 + (kl % 7); }
        xoffs[tid] = v;
    }
    if (tid < 160) {
        int pg = p0 + tid;
        rtab[tid] = (pg < HW) ? ((pg / WO) - h0) * 32 + (pg % WO) : -1;
    }

    const float* xb = x    + (size_t)b * 256 * 961;
    const float* kb = kern + (size_t)b * CKK;

    auto stage_xk_direct = [&](int gg, int s) {   // prologue only
        float* xs = (float*)(smem + SM_X + s * XBUFB);
        float* km = (float*)(smem + SM_KM + s * 448);
#pragma unroll
        for (int i = 0; i < 4; i++) {
            int id = tid + i * 256;
            if (id < 2 * XSTG) {
                int ch = id >= XSTG, ii = id - ch * XSTG;
                float v = (h0 * 31 + ii < 961) ? xb[(size_t)(gg * 2 + ch) * 961 + h0 * 31 + ii] : 0.f;
                xs[ch * XCH + (ii / 31) * 32 + (ii % 31)] = v;
            }
        }
        if (tid < KG) km[tid] = (tid < 98) ? kb[(size_t)gg * 98 + tid] : 0.f;
    };
    auto build_B = [&](int s) {
        char* bt = smem + SM_B + s * B_BUF;
        float* xs = (float*)(smem + SM_X + s * XBUFB);
        float* km = (float*)(smem + SM_KM + s * 448);
#pragma unroll
        for (int it = 0; it < 9; it++) {
            int task = it * 256 + tid;
            if (task < 2240) {
                int p = task / 14, ch = task - (task / 14) * 14;
                int rb = rtab[p];
                uint4 val = make_uint4(0, 0, 0, 0);
                if (rb >= 0) {
                    int k0 = ch * 8;
                    const float4 km0 = *(const float4*)(km + k0);
                    const float4 km1 = *(const float4*)(km + k0 + 4);
                    const int4 xo0 = *(const int4*)(xoffs + k0);
                    const int4 xo1 = *(const int4*)(xoffs + k0 + 4);
                    __half2 h0v = __floats2half2_rn(xs[rb + xo0.x] * km0.x, xs[rb + xo0.y] * km0.y);
                    __half2 h1v = __floats2half2_rn(xs[rb + xo0.z] * km0.z, xs[rb + xo0.w] * km0.w);
                    __half2 h2v = __floats2half2_rn(xs[rb + xo1.x] * km1.x, xs[rb + xo1.y] * km1.y);
                    __half2 h3v = __floats2half2_rn(xs[rb + xo1.z] * km1.z, xs[rb + xo1.w] * km1.w);
                    val = make_uint4(*(uint32_t*)&h0v, *(uint32_t*)&h1v,
                                     *(uint32_t*)&h2v, *(uint32_t*)&h3v);
                }
                *(uint4*)(bt + p * PITCHB + ch * 16) = val;
            }
        }
    };
    auto cpasync_A = [&](int gg) {
        const char* src = (const char*)&g_W[t][gg][0][0][0];
        uint32_t dst = sbase + SM_A + (gg & 1) * A_BUF;
#pragma unroll
        for (int i = 0; i < 15; i++) {
            int idx = i * 256 + tid;
            CP16(dst + idx * 16, src + idx * 16);
        }
        CP_COMMIT();
    };

    // ---------- prologue ----------
    cpasync_A(0);
    stage_xk_direct(0, 0);
    stage_xk_direct(1, 1);
    __syncthreads();
    build_B(0);
    CP_WAIT0();

    float acc[2][10][4];
#pragma unroll
    for (int mi = 0; mi < 2; mi++)
#pragma unroll
        for (int j = 0; j < 10; j++)
#pragma unroll
            for (int q = 0; q < 4; q++) acc[mi][j][q] = 0.f;

    const uint32_t apat = (uint32_t)((mw * 32 + (lid & 15)) * PITCHB + (lid >> 4) * 16);
    const uint32_t bpat = (uint32_t)((nw * 80 + (lid & 7) + ((lid & 16) ? 8 : 0)) * PITCHB
                                     + ((lid & 8) ? 16 : 0));

    // ---------- main loop: ONE sync per group ----------
#pragma unroll 1
    for (int g = 0; g < NGROUP; g++) {
        const int buf = g & 1;
        __syncthreads();       // B(g), xs/km[(g+1)&1], A(g) all published

        if (g + 1 < NGROUP) cpasync_A(g + 1);

        float xv[4]; float kv = 0.f;
        if (g + 2 < NGROUP) {
#pragma unroll
            for (int i = 0; i < 4; i++) {
                int id = tid + i * 256;
                xv[i] = 0.f;
                if (id < 2 * XSTG) {
                    int ch = id >= XSTG, ii = id - ch * XSTG;
                    if (h0 * 31 + ii < 961)
                        xv[i] = xb[(size_t)((g + 2) * 2 + ch) * 961 + h0 * 31 + ii];
                }
            }
            if (tid < 98) kv = kb[(size_t)(g + 2) * 98 + tid];
        }

        // MMA(g)
        {
            const uint32_t ab = sbase + SM_A + buf * A_BUF + apat;
            const uint32_t bb = sbase + SM_B + buf * B_BUF + bpat;
#pragma unroll
            for (int k = 0; k < KSTEPS; k++) {
                uint32_t Ah0[4], Ah1[4], Al0[4], Al1[4], Bv[20];
                ldsm4(Ah0, ab + k * 32);
                ldsm4(Ah1, ab + 3840 + k * 32);
                ldsm4(Al0, ab + A_HALF + k * 32);
                ldsm4(Al1, ab + A_HALF + 3840 + k * 32);
#pragma unroll
                for (int j5 = 0; j5 < 5; j5++) ldsm4(&Bv[j5 * 4], bb + j5 * 3840 + k * 32);
#pragma unroll
                for (int j = 0; j < 10; j++) {
                    const uint32_t* bf = &Bv[(j >> 1) * 4 + (j & 1) * 2];
                    mma_f16(acc[0][j], Ah0, bf);
                    mma_f16(acc[1][j], Ah1, bf);
                    mma_f16(acc[0][j], Al0, bf);
                    mma_f16(acc[1][j], Al1, bf);
                }
            }
        }

        if (g + 1 < NGROUP) build_B((g + 1) & 1);

        if (g + 2 < NGROUP) {
            float* xs = (float*)(smem + SM_X + buf * XBUFB);
            float* km = (float*)(smem + SM_KM + buf * 448);
#pragma unroll
            for (int i = 0; i < 4; i++) {
                int id = tid + i * 256;
                if (id < 2 * XSTG) {
                    int ch = id >= XSTG, ii = id - ch * XSTG;
                    xs[ch * XCH + (ii / 31) * 32 + (ii % 31)] = xv[i];
                }
            }
            if (tid < KG) km[tid] = (tid < 98) ? kv : 0.f;
        }

        CP_WAIT0();
    }

    // ---------- epilogue ----------
    const float s = 1.0f / 256.0f;
#pragma unroll
    for (int mi = 0; mi < 2; mi++) {
        int o = o0 + mw * 32 + mi * 16 + (lid >> 2);
        float bv0 = __ldg(bias + o);
        float bv1 = __ldg(bias + o + 8);
        float* r0 = out + ((size_t)b * O_ + o) * HW;
        float* r1 = r0 + 8 * HW;
#pragma unroll
        for (int j = 0; j < 10; j++) {
            int p = p0 + nw * 80 + j * 8 + 2 * (lid & 3);
            if (p < HW)     r0[p]     = acc[mi][j][0] * s + bv0;
            if (p + 1 < HW) r0[p + 1] = acc[mi][j][1] * s + bv0;
            if (p < HW)     r1[p]     = acc[mi][j][2] * s + bv1;
            if (p + 1 < HW) r1[p + 1] = acc[mi][j][3] * s + bv1;
        }
    }
}

extern "C" void kernel_launch(void* const* d_in, const int* in_sizes, int n_in,
                              void* d_out, int out_size) {
    const float* x      = (const float*)d_in[0];
    const float* kernel = (const float*)d_in[1];
    const float* weight = (const float*)d_in[2];
    const float* bias   = (const float*)d_in[3];
    float* out = (float*)d_out;

    cudaFuncSetAttribute(dwconv_hmma4, cudaFuncAttributeMaxDynamicSharedMemorySize, SMEM_DYN);

    precompute_w<<<14336, 256>>>(weight);
    dwconv_hmma4<<<256, THREADS, SMEM_DYN>>>(x, kernel, bias, out);
}

// round 8
// speedup vs baseline: 1.1838x; 1.1838x over previous
#include <cuda_runtime.h>
#include <cuda_fp16.h>
#include <cstdint>

#define B_  32
#define O_  256
#define KK  49
#define HW  625
#define WO  25
#define CKK 12544

#define THREADS 512          // 16 warps: 4(M) x 4(N)
#define NGROUP  128          // channel pairs
#define KG      112          // padded K per group (98 real)
#define KSTEPS  7
#define PITCH   120
#define PITCHB  240
#define A_TILE  30720        // 128 * 240 (hi only)
#define B_TILE  38400        // 160 * 240

#define XCH     448          // 14 rows * 32 floats per channel
#define XSTG    434          // 14 * 31 staged floats per channel
#define XBUFB   3584

#define SM_A    0            // 2 * 30720
#define SM_B    61440        // 2 * 38400
#define SM_X    138240       // 2 * 3584
#define SM_KM   145408       // 2 * 448
#define SM_XOFF 146304
#define SM_RTAB 146752
#define SMEM_DYN 147456

// Precomputed fp16 weights (x256), hi only: [t][g][o 128][k 120]
__device__ __half g_W[2][NGROUP][128][PITCH];

__device__ __forceinline__ uint32_t smem_u32(const void* p) {
    uint32_t a;
    asm("{ .reg .u64 t; cvta.to.shared.u64 t, %1; cvt.u32.u64 %0, t; }" : "=r"(a) : "l"(p));
    return a;
}
__device__ __forceinline__ void ldsm4(uint32_t* r, uint32_t addr) {
    asm volatile("ldmatrix.sync.aligned.m8n8.x4.shared.b16 {%0,%1,%2,%3}, [%4];"
                 : "=r"(r[0]), "=r"(r[1]), "=r"(r[2]), "=r"(r[3]) : "r"(addr));
}
__device__ __forceinline__ void ldsm2(uint32_t* r, uint32_t addr) {
    asm volatile("ldmatrix.sync.aligned.m8n8.x2.shared.b16 {%0,%1}, [%2];"
                 : "=r"(r[0]), "=r"(r[1]) : "r"(addr));
}
__device__ __forceinline__ void mma_f16(float* d, const uint32_t* a, const uint32_t* b) {
    asm volatile("mma.sync.aligned.m16n8k16.row.col.f32.f16.f16.f32 "
                 "{%0,%1,%2,%3}, {%4,%5,%6,%7}, {%8,%9}, {%0,%1,%2,%3};"
                 : "+f"(d[0]), "+f"(d[1]), "+f"(d[2]), "+f"(d[3])
                 : "r"(a[0]), "r"(a[1]), "r"(a[2]), "r"(a[3]), "r"(b[0]), "r"(b[1]));
}
#define CP16(dst, src) \
    asm volatile("cp.async.cg.shared.global [%0], [%1], 16;" :: "r"(dst), "l"(src) : "memory")
#define CP_COMMIT() asm volatile("cp.async.commit_group;" ::: "memory")
#define CP_WAIT0()  asm volatile("cp.async.wait_group 0;" ::: "memory")

__global__ void precompute_w(const float* __restrict__ w) {
    long idx = (long)blockIdx.x * 256 + threadIdx.x;   // [t][g][o][k<120]
    int k = idx % PITCH;
    int o = (idx / PITCH) & 127;
    int g = (idx / (PITCH * 128)) & 127;
    int t = (int)(idx / ((long)PITCH * 128 * NGROUP));
    if (t >= 2) return;
    float v = 0.f;
    if (k < 98) {
        int ci = k / 49, kl = k - ci * 49;
        v = w[(size_t)(t * 128 + o) * CKK + (g * 2 + ci) * KK + kl] * 256.f;
    }
    g_W[t][g][o][k] = __float2half_rn(v);
}

__global__ __launch_bounds__(THREADS, 1)
void dwconv_hmma5(const float* __restrict__ x, const float* __restrict__ kern,
                  const float* __restrict__ bias, float* __restrict__ out)
{
    extern __shared__ __align__(128) char smem[];
    const uint32_t sbase = smem_u32(smem);

    const int tid = threadIdx.x, wid = tid >> 5, lid = tid & 31;
    const int mw = wid >> 2, nw = wid & 3;
    const int blk = blockIdx.x;
    const int pt = blk & 3, t = (blk >> 2) & 1, b = blk >> 3;
    const int p0 = pt * 160, o0 = t * 128;
    const int h0 = p0 / WO;

    int* xoffs = (int*)(smem + SM_XOFF);
    int* rtab  = (int*)(smem + SM_RTAB);
    if (tid < KG) {
        int v = 0;
        if (tid < 98) { int ci = tid >= 49, kl = tid - ci * 49;
                        v = ci * XCH + (kl / 7) * 32 + (kl % 7); }
        xoffs[tid] = v;
    }
    if (tid < 160) {
        int pg = p0 + tid;
        rtab[tid] = (pg < HW) ? ((pg / WO) - h0) * 32 + (pg % WO) : -1;
    }

    const float* xb = x    + (size_t)b * 256 * 961;
    const float* kb = kern + (size_t)b * CKK;

    auto build_B = [&](int s) {
        char* bt = smem + SM_B + s * B_TILE;
        float* xs = (float*)(smem + SM_X + s * XBUFB);
        float* km = (float*)(smem + SM_KM + s * 448);
#pragma unroll
        for (int it = 0; it < 5; it++) {
            int task = it * 512 + tid;
            if (task < 2240) {
                int p = task / 14, ch = task - (task / 14) * 14;
                int rb = rtab[p];
                uint4 val = make_uint4(0, 0, 0, 0);
                if (rb >= 0) {
                    int k0 = ch * 8;
                    const float4 km0 = *(const float4*)(km + k0);
                    const float4 km1 = *(const float4*)(km + k0 + 4);
                    const int4 xo0 = *(const int4*)(xoffs + k0);
                    const int4 xo1 = *(const int4*)(xoffs + k0 + 4);
                    __half2 h0v = __floats2half2_rn(xs[rb + xo0.x] * km0.x, xs[rb + xo0.y] * km0.y);
                    __half2 h1v = __floats2half2_rn(xs[rb + xo0.z] * km0.z, xs[rb + xo0.w] * km0.w);
                    __half2 h2v = __floats2half2_rn(xs[rb + xo1.x] * km1.x, xs[rb + xo1.y] * km1.y);
                    __half2 h3v = __floats2half2_rn(xs[rb + xo1.z] * km1.z, xs[rb + xo1.w] * km1.w);
                    val = make_uint4(*(uint32_t*)&h0v, *(uint32_t*)&h1v,
                                     *(uint32_t*)&h2v, *(uint32_t*)&h3v);
                }
                *(uint4*)(bt + p * PITCHB + ch * 16) = val;
            }
        }
    };
    auto cpasync_A = [&](int gg) {
        const char* src = (const char*)&g_W[t][gg][0][0];
        uint32_t dst = sbase + SM_A + (gg & 1) * A_TILE;
#pragma unroll
        for (int i = 0; i < 4; i++) {
            int idx = i * 512 + tid;
            if (idx < 1920) CP16(dst + idx * 16, src + idx * 16);
        }
        CP_COMMIT();
    };

    // ---------- prologue: prefetch x(0), issue A(0) ----------
    cpasync_A(0);
    float xv[2], kv;
    {
        xv[0] = xv[1] = kv = 0.f;
#pragma unroll
        for (int i = 0; i < 2; i++) {
            int id = tid + i * 512;
            if (id < 2 * XSTG) {
                int ch = id >= XSTG, ii = id - ch * XSTG;
                if (h0 * 31 + ii < 961) xv[i] = xb[(size_t)ch * 961 + h0 * 31 + ii];
            }
        }
        if (tid < 98) kv = kb[tid];
    }

    float acc[2][5][4];
#pragma unroll
    for (int mi = 0; mi < 2; mi++)
#pragma unroll
        for (int j = 0; j < 5; j++)
#pragma unroll
            for (int q = 0; q < 4; q++) acc[mi][j][q] = 0.f;

    const uint32_t apat = (uint32_t)((mw * 32 + (lid & 15)) * PITCHB + (lid >> 4) * 16);
    const uint32_t bpat = (uint32_t)((nw * 40 + (lid & 7) + ((lid & 16) ? 8 : 0)) * PITCHB
                                     + ((lid & 8) ? 16 : 0));
    const int l2 = lid & 15;
    const uint32_t bpat2 = (uint32_t)((nw * 40 + 32 + (l2 & 7)) * PITCHB + ((l2 & 8) ? 16 : 0));

#pragma unroll 1
    for (int g = 0; g < NGROUP; g++) {
        const int buf = g & 1;

        // (a) stage prefetched x(g)/kern(g) into smem buffers
        {
            float* xs = (float*)(smem + SM_X + buf * XBUFB);
            float* km = (float*)(smem + SM_KM + buf * 448);
#pragma unroll
            for (int i = 0; i < 2; i++) {
                int id = tid + i * 512;
                if (id < 2 * XSTG) {
                    int ch = id >= XSTG, ii = id - ch * XSTG;
                    xs[ch * XCH + (ii / 31) * 32 + (ii % 31)] = xv[i];
                }
            }
            if (tid < KG) km[tid] = (tid < 98) ? kv : 0.f;
        }
        __syncthreads();                 // xs/km(g) ready; MMA(g-1) done

        // (c) build B(g)
        build_B(buf);

        // (d) prefetch x(g+1) into regs
        if (g + 1 < NGROUP) {
            xv[0] = xv[1] = kv = 0.f;
#pragma unroll
            for (int i = 0; i < 2; i++) {
                int id = tid + i * 512;
                if (id < 2 * XSTG) {
                    int ch = id >= XSTG, ii = id - ch * XSTG;
                    if (h0 * 31 + ii < 961)
                        xv[i] = xb[(size_t)((g + 1) * 2 + ch) * 961 + h0 * 31 + ii];
                }
            }
            if (tid < 98) kv = kb[(size_t)(g + 1) * 98 + tid];
        }

        CP_WAIT0();                      // A(g) arrived
        __syncthreads();                 // B(g) complete

        // (f) prefetch A(g+1)
        if (g + 1 < NGROUP) cpasync_A(g + 1);

        // (g) MMA(g): single product Ah x Bh
        {
            const uint32_t ab = sbase + SM_A + buf * A_TILE + apat;
            const uint32_t bb = sbase + SM_B + buf * B_TILE;
#pragma unroll
            for (int k = 0; k < KSTEPS; k++) {
                uint32_t A0[4], A1[4], Bv[10];
                ldsm4(A0, ab + k * 32);
                ldsm4(A1, ab + 3840 + k * 32);
                ldsm4(&Bv[0], bb + bpat  + k * 32);
                ldsm4(&Bv[4], bb + bpat  + 3840 + k * 32);
                ldsm2(&Bv[8], bb + bpat2 + k * 32);
#pragma unroll
                for (int j = 0; j < 5; j++) {
                    const uint32_t* bf = &Bv[j * 2];
                    mma_f16(acc[0][j], A0, bf);
                    mma_f16(acc[1][j], A1, bf);
                }
            }
        }
    }

    // ---------- epilogue ----------
    const float s = 1.0f / 256.0f;
#pragma unroll
    for (int mi = 0; mi < 2; mi++) {
        int o = o0 + mw * 32 + mi * 16 + (lid >> 2);
        float bv0 = __ldg(bias + o);
        float bv1 = __ldg(bias + o + 8);
        float* r0 = out + ((size_t)b * O_ + o) * HW;
        float* r1 = r0 + 8 * HW;
#pragma unroll
        for (int j = 0; j < 5; j++) {
            int p = p0 + nw * 40 + j * 8 + 2 * (lid & 3);
            if (p < HW)     r0[p]     = acc[mi][j][0] * s + bv0;
            if (p + 1 < HW) r0[p + 1] = acc[mi][j][1] * s + bv0;
            if (p < HW)     r1[p]     = acc[mi][j][2] * s + bv1;
            if (p + 1 < HW) r1[p + 1] = acc[mi][j][3] * s + bv1;
        }
    }
}

extern "C" void kernel_launch(void* const* d_in, const int* in_sizes, int n_in,
                              void* d_out, int out_size) {
    const float* x      = (const float*)d_in[0];
    const float* kernel = (const float*)d_in[1];
    const float* weight = (const float*)d_in[2];
    const float* bias   = (const float*)d_in[3];
    float* out = (float*)d_out;

    cudaFuncSetAttribute(dwconv_hmma5, cudaFuncAttributeMaxDynamicSharedMemorySize, SMEM_DYN);

    // 2 * 128 * 128 * 120 = 3,932,160 elements / 256 = 15360 blocks
    precompute_w<<<15360, 256>>>(weight);
    dwconv_hmma5<<<256, THREADS, SMEM_DYN>>>(x, kernel, bias, out);
}

// round 9
// speedup vs baseline: 2.2044x; 1.8621x over previous
#include <cuda_runtime.h>
#include <cuda_fp16.h>
#include <cstdint>

#define B_  32
#define O_  256
#define KK  49
#define HW  625
#define WO  25
#define CKK 12544

#define THREADS 512          // 16 warps: 4(M) x 4(N)
#define NGROUP  128          // channel pairs
#define KG      112          // k = ch*56 + ki*8 + kj (kj<7 real)
#define KSTEPS  7
#define PITCH   120
#define PITCHB  240
#define A_TILE  30720        // 128 * 240 (hi only)
#define B_TILE  38400        // 160 * 240

#define XCH     448          // 14 rows * 32 floats per channel
#define XSTG    434          // 14 * 31 staged floats per channel
#define XBUFB   3584

#define SM_A    0            // 2 * 30720
#define SM_B    61440        // 2 * 38400
#define SM_X    138240       // 2 * 3584
#define SM_KM   145408       // 2 * 448 bytes (112 floats each)
#define SM_RTAB 146304       // 160 ints
#define SMEM_DYN 147456

// Precomputed fp16 weights (x256), hi only, new k layout: [t][g][o 128][k 120]
__device__ __half g_W[2][NGROUP][128][PITCH];

__device__ __forceinline__ uint32_t smem_u32(const void* p) {
    uint32_t a;
    asm("{ .reg .u64 t; cvta.to.shared.u64 t, %1; cvt.u32.u64 %0, t; }" : "=r"(a) : "l"(p));
    return a;
}
__device__ __forceinline__ void ldsm4(uint32_t* r, uint32_t addr) {
    asm volatile("ldmatrix.sync.aligned.m8n8.x4.shared.b16 {%0,%1,%2,%3}, [%4];"
                 : "=r"(r[0]), "=r"(r[1]), "=r"(r[2]), "=r"(r[3]) : "r"(addr));
}
__device__ __forceinline__ void ldsm2(uint32_t* r, uint32_t addr) {
    asm volatile("ldmatrix.sync.aligned.m8n8.x2.shared.b16 {%0,%1}, [%2];"
                 : "=r"(r[0]), "=r"(r[1]) : "r"(addr));
}
__device__ __forceinline__ void mma_f16(float* d, const uint32_t* a, const uint32_t* b) {
    asm volatile("mma.sync.aligned.m16n8k16.row.col.f32.f16.f16.f32 "
                 "{%0,%1,%2,%3}, {%4,%5,%6,%7}, {%8,%9}, {%0,%1,%2,%3};"
                 : "+f"(d[0]), "+f"(d[1]), "+f"(d[2]), "+f"(d[3])
                 : "r"(a[0]), "r"(a[1]), "r"(a[2]), "r"(a[3]), "r"(b[0]), "r"(b[1]));
}
#define CP16(dst, src) \
    asm volatile("cp.async.cg.shared.global [%0], [%1], 16;" :: "r"(dst), "l"(src) : "memory")
#define CP_COMMIT() asm volatile("cp.async.commit_group;" ::: "memory")
#define CP_WAIT0()  asm volatile("cp.async.wait_group 0;" ::: "memory")

__global__ void precompute_w(const float* __restrict__ w) {
    long idx = (long)blockIdx.x * 256 + threadIdx.x;   // [t][g][o][k<120]
    int k = idx % PITCH;
    int o = (idx / PITCH) & 127;
    int g = (idx / (PITCH * 128)) & 127;
    int t = (int)(idx / ((long)PITCH * 128 * NGROUP));
    if (t >= 2) return;
    float v = 0.f;
    if (k < KG) {
        int ch = k / 56, r = (k % 56) / 8, kj = k & 7;
        if (kj < 7)
            v = w[(size_t)(t * 128 + o) * CKK + (g * 2 + ch) * KK + r * 7 + kj] * 256.f;
    }
    g_W[t][g][o][k] = __float2half_rn(v);
}

__global__ __launch_bounds__(THREADS, 1)
void dwconv_hmma6(const float* __restrict__ x, const float* __restrict__ kern,
                  const float* __restrict__ bias, float* __restrict__ out)
{
    extern __shared__ __align__(128) char smem[];
    const uint32_t sbase = smem_u32(smem);

    const int tid = threadIdx.x, wid = tid >> 5, lid = tid & 31;
    const int mw = wid >> 2, nw = wid & 3;
    const int blk = blockIdx.x;
    const int pt = blk & 3, t = (blk >> 2) & 1, b = blk >> 3;
    const int p0 = pt * 160, o0 = t * 128;
    const int h0 = p0 / WO;

    int* rtab = (int*)(smem + SM_RTAB);
    if (tid < 160) {
        int pg = p0 + tid;
        rtab[tid] = (pg < HW) ? ((pg / WO) - h0) * 32 + (pg % WO) : -1;
    }

    const float* xb = x    + (size_t)b * 256 * 961;
    const float* kb = kern + (size_t)b * CKK;

    // k-mapped kern gather: tid<112 -> kern value for (ch, ki, kj)
    auto kern_fetch = [&](int gg) -> float {
        if (tid >= KG) return 0.f;
        int ch = tid / 56, r = (tid % 56) / 8, kj = tid & 7;
        if (kj >= 7) return 0.f;
        return kb[(size_t)(gg * 2 + ch) * KK + r * 7 + kj];
    };

    // conflict-free row-oriented B build
    auto build_B = [&](int s) {
        char* bt = smem + SM_B + s * B_TILE;
        const float* xs = (const float*)(smem + SM_X + s * XBUFB);
        const float* km = (const float*)(smem + SM_KM + s * 448);
#pragma unroll
        for (int it = 0; it < 5; it++) {
            int wt = it * 16 + wid;        // 70 warp-tasks: 5 p-grp x 2 ch x 7 ki
            if (wt < 70) {
                int pg5 = wt / 14;
                int rem = wt - pg5 * 14;
                int ch = rem / 7, ki = rem - (rem / 7) * 7;
                int p = pg5 * 32 + lid;
                int rb = rtab[p];
                uint4 val = make_uint4(0, 0, 0, 0);
                if (rb >= 0) {
                    const float* kp = km + ch * 56 + ki * 8;
                    const float4 ka = *(const float4*)kp;
                    const float4 kc = *(const float4*)(kp + 4);
                    const float* xp = xs + ch * XCH + rb + ki * 32;
                    __half2 h0v = __floats2half2_rn(xp[0] * ka.x, xp[1] * ka.y);
                    __half2 h1v = __floats2half2_rn(xp[2] * ka.z, xp[3] * ka.w);
                    __half2 h2v = __floats2half2_rn(xp[4] * kc.x, xp[5] * kc.y);
                    __half2 h3v = __floats2half2_rn(xp[6] * kc.z, 0.f);
                    val = make_uint4(*(uint32_t*)&h0v, *(uint32_t*)&h1v,
                                     *(uint32_t*)&h2v, *(uint32_t*)&h3v);
                }
                *(uint4*)(bt + p * PITCHB + (ch * 7 + ki) * 16) = val;
            }
        }
    };
    auto cpasync_A = [&](int gg) {
        const char* src = (const char*)&g_W[t][gg][0][0];
        uint32_t dst = sbase + SM_A + (gg & 1) * A_TILE;
#pragma unroll
        for (int i = 0; i < 4; i++) {
            int idx = i * 512 + tid;
            if (idx < 1920) CP16(dst + idx * 16, src + idx * 16);
        }
        CP_COMMIT();
    };

    // ---------- prologue: prefetch x(0), issue A(0) ----------
    cpasync_A(0);
    float xv[2], kv;
    {
        xv[0] = xv[1] = 0.f;
#pragma unroll
        for (int i = 0; i < 2; i++) {
            int id = tid + i * 512;
            if (id < 2 * XSTG) {
                int ch = id >= XSTG, ii = id - ch * XSTG;
                if (h0 * 31 + ii < 961) xv[i] = xb[(size_t)ch * 961 + h0 * 31 + ii];
            }
        }
        kv = kern_fetch(0);
    }

    float acc[2][5][4];
#pragma unroll
    for (int mi = 0; mi < 2; mi++)
#pragma unroll
        for (int j = 0; j < 5; j++)
#pragma unroll
            for (int q = 0; q < 4; q++) acc[mi][j][q] = 0.f;

    const uint32_t apat = (uint32_t)((mw * 32 + (lid & 15)) * PITCHB + (lid >> 4) * 16);
    const uint32_t bpat = (uint32_t)((nw * 40 + (lid & 7) + ((lid & 16) ? 8 : 0)) * PITCHB
                                     + ((lid & 8) ? 16 : 0));
    const int l2 = lid & 15;
    const uint32_t bpat2 = (uint32_t)((nw * 40 + 32 + (l2 & 7)) * PITCHB + ((l2 & 8) ? 16 : 0));

#pragma unroll 1
    for (int g = 0; g < NGROUP; g++) {
        const int buf = g & 1;

        // (a) stage prefetched x(g)/kern(g) into smem buffers
        {
            float* xs = (float*)(smem + SM_X + buf * XBUFB);
            float* km = (float*)(smem + SM_KM + buf * 448);
#pragma unroll
            for (int i = 0; i < 2; i++) {
                int id = tid + i * 512;
                if (id < 2 * XSTG) {
                    int ch = id >= XSTG, ii = id - ch * XSTG;
                    xs[ch * XCH + (ii / 31) * 32 + (ii % 31)] = xv[i];
                }
            }
            if (tid < KG) km[tid] = kv;
        }
        __syncthreads();                 // xs/km(g) ready; MMA(g-1) done

        // (c) build B(g)
        build_B(buf);

        // (d) prefetch x(g+1) into regs
        if (g + 1 < NGROUP) {
            xv[0] = xv[1] = 0.f;
#pragma unroll
            for (int i = 0; i < 2; i++) {
                int id = tid + i * 512;
                if (id < 2 * XSTG) {
                    int ch = id >= XSTG, ii = id - ch * XSTG;
                    if (h0 * 31 + ii < 961)
                        xv[i] = xb[(size_t)((g + 1) * 2 + ch) * 961 + h0 * 31 + ii];
                }
            }
            kv = kern_fetch(g + 1);
        }

        CP_WAIT0();                      // A(g) arrived
        __syncthreads();                 // B(g) complete

        // (f) prefetch A(g+1)
        if (g + 1 < NGROUP) cpasync_A(g + 1);

        // (g) MMA(g): single product Ah x Bh
        {
            const uint32_t ab = sbase + SM_A + buf * A_TILE + apat;
            const uint32_t bb = sbase + SM_B + buf * B_TILE;
#pragma unroll
            for (int k = 0; k < KSTEPS; k++) {
                uint32_t A0[4], A1[4], Bv[10];
                ldsm4(A0, ab + k * 32);
                ldsm4(A1, ab + 3840 + k * 32);
                ldsm4(&Bv[0], bb + bpat  + k * 32);
                ldsm4(&Bv[4], bb + bpat  + 3840 + k * 32);
                ldsm2(&Bv[8], bb + bpat2 + k * 32);
#pragma unroll
                for (int j = 0; j < 5; j++) {
                    const uint32_t* bf = &Bv[j * 2];
                    mma_f16(acc[0][j], A0, bf);
                    mma_f16(acc[1][j], A1, bf);
                }
            }
        }
    }

    // ---------- epilogue ----------
    const float s = 1.0f / 256.0f;
#pragma unroll
    for (int mi = 0; mi < 2; mi++) {
        int o = o0 + mw * 32 + mi * 16 + (lid >> 2);
        float bv0 = __ldg(bias + o);
        float bv1 = __ldg(bias + o + 8);
        float* r0 = out + ((size_t)b * O_ + o) * HW;
        float* r1 = r0 + 8 * HW;
#pragma unroll
        for (int j = 0; j < 5; j++) {
            int p = p0 + nw * 40 + j * 8 + 2 * (lid & 3);
            if (p < HW)     r0[p]     = acc[mi][j][0] * s + bv0;
            if (p + 1 < HW) r0[p + 1] = acc[mi][j][1] * s + bv0;
            if (p < HW)     r1[p]     = acc[mi][j][2] * s + bv1;
            if (p + 1 < HW) r1[p + 1] = acc[mi][j][3] * s + bv1;
        }
    }
}

extern "C" void kernel_launch(void* const* d_in, const int* in_sizes, int n_in,
                              void* d_out, int out_size) {
    const float* x      = (const float*)d_in[0];
    const float* kernel = (const float*)d_in[1];
    const float* weight = (const float*)d_in[2];
    const float* bias   = (const float*)d_in[3];
    float* out = (float*)d_out;

    cudaFuncSetAttribute(dwconv_hmma6, cudaFuncAttributeMaxDynamicSharedMemorySize, SMEM_DYN);

    precompute_w<<<15360, 256>>>(weight);
    dwconv_hmma6<<<256, THREADS, SMEM_DYN>>>(x, kernel, bias, out);
}

// round 10
// speedup vs baseline: 2.2610x; 1.0257x over previous
#include <cuda_runtime.h>
#include <cuda_fp16.h>
#include <cstdint>

#define B_  32
#define O_  256
#define KK  49
#define HW  625
#define WO  25
#define CKK 12544

#define THREADS 512          // 16 warps: 4(M) x 4(N)
#define NGROUP  128          // channel pairs
#define KG      112          // k = ch*56 + ki*8 + kj (kj<7 real)
#define KSTEPS  7
#define PITCH   120
#define PITCHB  240
#define A_TILE  30720        // 128 * 240 (hi only)
#define B_TILE  38400        // 160 * 240

#define XCH     448          // 14 rows * 32 floats per channel
#define XSTG    434          // 14 * 31 staged floats per channel
#define XBUFB   3584

#define SM_A    0            // 2 * 30720
#define SM_B    61440        // 2 * 38400
#define SM_X    138240       // 2 * 3584
#define SM_KM   145408       // 2 * 448 bytes
#define SM_RTAB 146304       // 160 ints
#define SMEM_DYN 147456

// Precomputed fp16 weights (x256), hi only: [t][g][o 128][k 120]
__device__ __half g_W[2][NGROUP][128][PITCH];

__device__ __forceinline__ uint32_t smem_u32(const void* p) {
    uint32_t a;
    asm("{ .reg .u64 t; cvta.to.shared.u64 t, %1; cvt.u32.u64 %0, t; }" : "=r"(a) : "l"(p));
    return a;
}
__device__ __forceinline__ void ldsm4(uint32_t* r, uint32_t addr) {
    asm volatile("ldmatrix.sync.aligned.m8n8.x4.shared.b16 {%0,%1,%2,%3}, [%4];"
                 : "=r"(r[0]), "=r"(r[1]), "=r"(r[2]), "=r"(r[3]) : "r"(addr));
}
__device__ __forceinline__ void ldsm2(uint32_t* r, uint32_t addr) {
    asm volatile("ldmatrix.sync.aligned.m8n8.x2.shared.b16 {%0,%1}, [%2];"
                 : "=r"(r[0]), "=r"(r[1]) : "r"(addr));
}
__device__ __forceinline__ void mma_f16(float* d, const uint32_t* a, const uint32_t* b) {
    asm volatile("mma.sync.aligned.m16n8k16.row.col.f32.f16.f16.f32 "
                 "{%0,%1,%2,%3}, {%4,%5,%6,%7}, {%8,%9}, {%0,%1,%2,%3};"
                 : "+f"(d[0]), "+f"(d[1]), "+f"(d[2]), "+f"(d[3])
                 : "r"(a[0]), "r"(a[1]), "r"(a[2]), "r"(a[3]), "r"(b[0]), "r"(b[1]));
}
#define CP16(dst, src) \
    asm volatile("cp.async.cg.shared.global [%0], [%1], 16;" :: "r"(dst), "l"(src) : "memory")
#define CP_COMMIT() asm volatile("cp.async.commit_group;" ::: "memory")
#define CP_WAIT0()  asm volatile("cp.async.wait_group 0;" ::: "memory")

__global__ void precompute_w(const float* __restrict__ w) {
    long idx = (long)blockIdx.x * 256 + threadIdx.x;   // [t][g][o][k<120]
    int k = idx % PITCH;
    int o = (idx / PITCH) & 127;
    int g = (idx / (PITCH * 128)) & 127;
    int t = (int)(idx / ((long)PITCH * 128 * NGROUP));
    if (t >= 2) return;
    float v = 0.f;
    if (k < KG) {
        int ch = k / 56, r = (k % 56) / 8, kj = k & 7;
        if (kj < 7)
            v = w[(size_t)(t * 128 + o) * CKK + (g * 2 + ch) * KK + r * 7 + kj] * 256.f;
    }
    g_W[t][g][o][k] = __float2half_rn(v);
}

__global__ __launch_bounds__(THREADS, 1)
void dwconv_hmma7(const float* __restrict__ x, const float* __restrict__ kern,
                  const float* __restrict__ bias, float* __restrict__ out)
{
    extern __shared__ __align__(128) char smem[];
    const uint32_t sbase = smem_u32(smem);

    const int tid = threadIdx.x, wid = tid >> 5, lid = tid & 31;
    const int mw = wid >> 2, nw = wid & 3;
    const int blk = blockIdx.x;
    const int pt = blk & 3, t = (blk >> 2) & 1, b = blk >> 3;
    const int p0 = pt * 160, o0 = t * 128;
    const int h0 = p0 / WO;

    int* rtab = (int*)(smem + SM_RTAB);
    if (tid < 160) {
        int pg = p0 + tid;
        rtab[tid] = (pg < HW) ? ((pg / WO) - h0) * 32 + (pg % WO) : -1;
    }

    const float* xb = x    + (size_t)b * 256 * 961;
    const float* kb = kern + (size_t)b * CKK;

    auto kern_fetch = [&](int gg) -> float {
        if (tid >= KG) return 0.f;
        int ch = tid / 56, r = (tid % 56) / 8, kj = tid & 7;
        if (kj >= 7) return 0.f;
        return kb[(size_t)(gg * 2 + ch) * KK + r * 7 + kj];
    };

    // conflict-free row-oriented B build: B(group gg) lives in buf gg&1
    auto build_B = [&](int s) {
        char* bt = smem + SM_B + s * B_TILE;
        const float* xs = (const float*)(smem + SM_X + s * XBUFB);
        const float* km = (const float*)(smem + SM_KM + s * 448);
#pragma unroll
        for (int it = 0; it < 5; it++) {
            int wt = it * 16 + wid;        // 70 warp-tasks: 5 p-grp x 2 ch x 7 ki
            if (wt < 70) {
                int pg5 = wt / 14;
                int rem = wt - pg5 * 14;
                int ch = rem / 7, ki = rem - (rem / 7) * 7;
                int p = pg5 * 32 + lid;
                int rb = rtab[p];
                uint4 val = make_uint4(0, 0, 0, 0);
                if (rb >= 0) {
                    const float* kp = km + ch * 56 + ki * 8;
                    const float4 ka = *(const float4*)kp;
                    const float4 kc = *(const float4*)(kp + 4);
                    const float* xp = xs + ch * XCH + rb + ki * 32;
                    __half2 h0v = __floats2half2_rn(xp[0] * ka.x, xp[1] * ka.y);
                    __half2 h1v = __floats2half2_rn(xp[2] * ka.z, xp[3] * ka.w);
                    __half2 h2v = __floats2half2_rn(xp[4] * kc.x, xp[5] * kc.y);
                    __half2 h3v = __floats2half2_rn(xp[6] * kc.z, 0.f);
                    val = make_uint4(*(uint32_t*)&h0v, *(uint32_t*)&h1v,
                                     *(uint32_t*)&h2v, *(uint32_t*)&h3v);
                }
                *(uint4*)(bt + p * PITCHB + (ch * 7 + ki) * 16) = val;
            }
        }
    };
    auto cpasync_A = [&](int gg) {
        const char* src = (const char*)&g_W[t][gg][0][0];
        uint32_t dst = sbase + SM_A + (gg & 1) * A_TILE;
#pragma unroll
        for (int i = 0; i < 4; i++) {
            int idx = i * 512 + tid;
            if (idx < 1920) CP16(dst + idx * 16, src + idx * 16);
        }
        CP_COMMIT();
    };
    auto stage_xk_direct = [&](int gg) {   // prologue only: LDG -> STS, buf gg&1
        float* xs = (float*)(smem + SM_X + (gg & 1) * XBUFB);
        float* km = (float*)(smem + SM_KM + (gg & 1) * 448);
#pragma unroll
        for (int i = 0; i < 2; i++) {
            int id = tid + i * 512;
            if (id < 2 * XSTG) {
                int ch = id >= XSTG, ii = id - ch * XSTG;
                float v = (h0 * 31 + ii < 961) ? xb[(size_t)(gg * 2 + ch) * 961 + h0 * 31 + ii] : 0.f;
                xs[ch * XCH + (ii / 31) * 32 + (ii % 31)] = v;
            }
        }
        if (tid < KG) km[tid] = kern_fetch(gg);
    };

    // ---------- prologue ----------
    cpasync_A(0);
    stage_xk_direct(0);
    stage_xk_direct(1);
    __syncthreads();           // xs/km(0),(1) + rtab visible
    build_B(0);
    CP_WAIT0();                // A(0) in

    float acc[2][5][4];
#pragma unroll
    for (int mi = 0; mi < 2; mi++)
#pragma unroll
        for (int j = 0; j < 5; j++)
#pragma unroll
            for (int q = 0; q < 4; q++) acc[mi][j][q] = 0.f;

    const uint32_t apat = (uint32_t)((mw * 32 + (lid & 15)) * PITCHB + (lid >> 4) * 16);
    const uint32_t bpat = (uint32_t)((nw * 40 + (lid & 7) + ((lid & 16) ? 8 : 0)) * PITCHB
                                     + ((lid & 8) ? 16 : 0));
    const int l2 = lid & 15;
    const uint32_t bpat2 = (uint32_t)((nw * 40 + 32 + (l2 & 7)) * PITCHB + ((l2 & 8) ? 16 : 0));

    // ---------- main loop: ONE sync per group ----------
#pragma unroll 1
    for (int g = 0; g < NGROUP; g++) {
        const int buf = g & 1;
        __syncthreads();   // publishes: B(g) [prev iter build], xs/km(g+1), A(g)

        // A(g+1) fetch into opposite buffer (disjoint from MMA(g) reads)
        if (g + 1 < NGROUP) cpasync_A(g + 1);

        // prefetch x(g+2)/kern(g+2) into regs
        float xv0 = 0.f, xv1 = 0.f, kv = 0.f;
        if (g + 2 < NGROUP) {
            {
                int id = tid;
                if (id < 2 * XSTG) {
                    int ch = id >= XSTG, ii = id - ch * XSTG;
                    if (h0 * 31 + ii < 961)
                        xv0 = xb[(size_t)((g + 2) * 2 + ch) * 961 + h0 * 31 + ii];
                }
            }
            {
                int id = tid + 512;
                if (id < 2 * XSTG) {
                    int ch = id >= XSTG, ii = id - ch * XSTG;
                    if (h0 * 31 + ii < 961)
                        xv1 = xb[(size_t)((g + 2) * 2 + ch) * 961 + h0 * 31 + ii];
                }
            }
            kv = kern_fetch(g + 2);
        }

        // MMA(g) — ptxas interleaves the build below into HMMA stalls
        {
            const uint32_t ab = sbase + SM_A + buf * A_TILE + apat;
            const uint32_t bb = sbase + SM_B + buf * B_TILE;
#pragma unroll
            for (int k = 0; k < KSTEPS; k++) {
                uint32_t A0[4], A1[4], Bv[10];
                ldsm4(A0, ab + k * 32);
                ldsm4(A1, ab + 3840 + k * 32);
                ldsm4(&Bv[0], bb + bpat  + k * 32);
                ldsm4(&Bv[4], bb + bpat  + 3840 + k * 32);
                ldsm2(&Bv[8], bb + bpat2 + k * 32);
#pragma unroll
                for (int j = 0; j < 5; j++) {
                    const uint32_t* bf = &Bv[j * 2];
                    mma_f16(acc[0][j], A0, bf);
                    mma_f16(acc[1][j], A1, bf);
                }
            }
        }

        // build B(g+1) into buf (g+1)&1 (disjoint from B(g) reads)
        if (g + 1 < NGROUP) build_B((g + 1) & 1);

        // stage x(g+2)/km(g+2) into buf g&1 (B(g)/xs(g) no longer needed after MMA(g);
        // all warps passed the top-of-iter sync, and xs[g&1] readers (build_B(g), prev
        // iter) finished before that sync)
        if (g + 2 < NGROUP) {
            float* xs = (float*)(smem + SM_X + buf * XBUFB);
            float* km = (float*)(smem + SM_KM + buf * 448);
            {
                int id = tid;
                if (id < 2 * XSTG) {
                    int ch = id >= XSTG, ii = id - ch * XSTG;
                    xs[ch * XCH + (ii / 31) * 32 + (ii % 31)] = xv0;
                }
            }
            {
                int id = tid + 512;
                if (id < 2 * XSTG) {
                    int ch = id >= XSTG, ii = id - ch * XSTG;
                    xs[ch * XCH + (ii / 31) * 32 + (ii % 31)] = xv1;
                }
            }
            if (tid < KG) km[tid] = kv;
        }

        CP_WAIT0();        // A(g+1) arrived (published by next iter's sync)
    }

    // ---------- epilogue ----------
    const float s = 1.0f / 256.0f;
#pragma unroll
    for (int mi = 0; mi < 2; mi++) {
        int o = o0 + mw * 32 + mi * 16 + (lid >> 2);
        float bv0 = __ldg(bias + o);
        float bv1 = __ldg(bias + o + 8);
        float* r0 = out + ((size_t)b * O_ + o) * HW;
        float* r1 = r0 + 8 * HW;
#pragma unroll
        for (int j = 0; j < 5; j++) {
            int p = p0 + nw * 40 + j * 8 + 2 * (lid & 3);
            if (p < HW)     r0[p]     = acc[mi][j][0] * s + bv0;
            if (p + 1 < HW) r0[p + 1] = acc[mi][j][1] * s + bv0;
            if (p < HW)     r1[p]     = acc[mi][j][2] * s + bv1;
            if (p + 1 < HW) r1[p + 1] = acc[mi][j][3] * s + bv1;
        }
    }
}

extern "C" void kernel_launch(void* const* d_in, const int* in_sizes, int n_in,
                              void* d_out, int out_size) {
    const float* x      = (const float*)d_in[0];
    const float* kernel = (const float*)d_in[1];
    const float* weight = (const float*)d_in[2];
    const float* bias   = (const float*)d_in[3];
    float* out = (float*)d_out;

    cudaFuncSetAttribute(dwconv_hmma7, cudaFuncAttributeMaxDynamicSharedMemorySize, SMEM_DYN);

    precompute_w<<<15360, 256>>>(weight);
    dwconv_hmma7<<<256, THREADS, SMEM_DYN>>>(x, kernel, bias, out);
}

// round 11
// speedup vs baseline: 2.2720x; 1.0049x over previous
#include <cuda_runtime.h>
#include <cuda_fp16.h>
#include <cstdint>

#define B_  32
#define O_  256
#define KK  49
#define HW  625
#define WO  25
#define CKK 12544

#define THREADS 256          // 8 warps: 4(M) x 2(N)
#define NGROUP  128          // channel pairs
#define KG      112          // k = ch*56 + ki*8 + kj (kj<7 real)
#define KSTEPS  7
#define PITCH   120
#define PITCHB  240
#define NT      80           // pixels per CTA
#define A_TILE  30720        // 128 * 240 (hi only)
#define B_TILE  19200        // 80 * 240

#define XCH     320          // 10 rows * 32 floats per channel (80px spans <=4 out rows)
#define XSTG    310          // 10 * 31 staged floats per channel
#define XBUFB   2560         // 2ch * 320 * 4B

#define SM_A    0            // 2 * 30720 = 61440
#define SM_B    61440        // 2 * 19200 = 38400
#define SM_X    99840        // 2 * 2560
#define SM_KM   104960       // 2 * 448
#define SM_RTAB 105856       // 96 ints
#define SMEM_DYN 106496

// Precomputed fp16 weights (x256), hi only: [t][g][o 128][k 120]
__device__ __half g_W[2][NGROUP][128][PITCH];

__device__ __forceinline__ uint32_t smem_u32(const void* p) {
    uint32_t a;
    asm("{ .reg .u64 t; cvta.to.shared.u64 t, %1; cvt.u32.u64 %0, t; }" : "=r"(a) : "l"(p));
    return a;
}
__device__ __forceinline__ void ldsm4(uint32_t* r, uint32_t addr) {
    asm volatile("ldmatrix.sync.aligned.m8n8.x4.shared.b16 {%0,%1,%2,%3}, [%4];"
                 : "=r"(r[0]), "=r"(r[1]), "=r"(r[2]), "=r"(r[3]) : "r"(addr));
}
__device__ __forceinline__ void ldsm2(uint32_t* r, uint32_t addr) {
    asm volatile("ldmatrix.sync.aligned.m8n8.x2.shared.b16 {%0,%1}, [%2];"
                 : "=r"(r[0]), "=r"(r[1]) : "r"(addr));
}
__device__ __forceinline__ void mma_f16(float* d, const uint32_t* a, const uint32_t* b) {
    asm volatile("mma.sync.aligned.m16n8k16.row.col.f32.f16.f16.f32 "
                 "{%0,%1,%2,%3}, {%4,%5,%6,%7}, {%8,%9}, {%0,%1,%2,%3};"
                 : "+f"(d[0]), "+f"(d[1]), "+f"(d[2]), "+f"(d[3])
                 : "r"(a[0]), "r"(a[1]), "r"(a[2]), "r"(a[3]), "r"(b[0]), "r"(b[1]));
}
#define CP16(dst, src) \
    asm volatile("cp.async.cg.shared.global [%0], [%1], 16;" :: "r"(dst), "l"(src) : "memory")
#define CP_COMMIT() asm volatile("cp.async.commit_group;" ::: "memory")
#define CP_WAIT0()  asm volatile("cp.async.wait_group 0;" ::: "memory")

__global__ void precompute_w(const float* __restrict__ w) {
    long idx = (long)blockIdx.x * 256 + threadIdx.x;   // [t][g][o][k<120]
    int k = idx % PITCH;
    int o = (idx / PITCH) & 127;
    int g = (idx / (PITCH * 128)) & 127;
    int t = (int)(idx / ((long)PITCH * 128 * NGROUP));
    if (t >= 2) return;
    float v = 0.f;
    if (k < KG) {
        int ch = k / 56, r = (k % 56) / 8, kj = k & 7;
        if (kj < 7)
            v = w[(size_t)(t * 128 + o) * CKK + (g * 2 + ch) * KK + r * 7 + kj] * 256.f;
    }
    g_W[t][g][o][k] = __float2half_rn(v);
}

__global__ __launch_bounds__(THREADS, 2)
void dwconv_hmma8(const float* __restrict__ x, const float* __restrict__ kern,
                  const float* __restrict__ bias, float* __restrict__ out)
{
    extern __shared__ __align__(128) char smem[];
    const uint32_t sbase = smem_u32(smem);

    const int tid = threadIdx.x, wid = tid >> 5, lid = tid & 31;
    const int mw = wid >> 1, nw = wid & 1;
    const int blk = blockIdx.x;
    const int pt = blk & 7, t = (blk >> 3) & 1, b = blk >> 4;
    const int p0 = pt * NT, o0 = t * 128;
    const int h0 = p0 / WO;

    int* rtab = (int*)(smem + SM_RTAB);
    if (tid < 96) {
        int pg = p0 + tid;
        rtab[tid] = (tid < NT && pg < HW) ? ((pg / WO) - h0) * 32 + (pg % WO) : -1;
    }

    const float* xb = x    + (size_t)b * 256 * 961;
    const float* kb = kern + (size_t)b * CKK;

    auto kern_fetch = [&](int gg) -> float {
        if (tid >= KG) return 0.f;
        int ch = tid / 56, r = (tid % 56) / 8, kj = tid & 7;
        if (kj >= 7) return 0.f;
        return kb[(size_t)(gg * 2 + ch) * KK + r * 7 + kj];
    };

    // conflict-free row-oriented B build: B(group gg) in buf gg&1
    auto build_B = [&](int s) {
        char* bt = smem + SM_B + s * B_TILE;
        const float* xs = (const float*)(smem + SM_X + s * XBUFB);
        const float* km = (const float*)(smem + SM_KM + s * 448);
#pragma unroll
        for (int it = 0; it < 6; it++) {
            int wt = it * 8 + wid;         // 42 warp-tasks: 3 p-grp x 2 ch x 7 ki
            if (wt < 42) {
                int pg3 = wt / 14;
                int rem = wt - pg3 * 14;
                int ch = rem / 7, ki = rem - (rem / 7) * 7;
                int p = pg3 * 32 + lid;
                if (p < NT) {
                    int rb = rtab[p];
                    uint4 val = make_uint4(0, 0, 0, 0);
                    if (rb >= 0) {
                        const float* kp = km + ch * 56 + ki * 8;
                        const float4 ka = *(const float4*)kp;
                        const float4 kc = *(const float4*)(kp + 4);
                        const float* xp = xs + ch * XCH + rb + ki * 32;
                        __half2 h0v = __floats2half2_rn(xp[0] * ka.x, xp[1] * ka.y);
                        __half2 h1v = __floats2half2_rn(xp[2] * ka.z, xp[3] * ka.w);
                        __half2 h2v = __floats2half2_rn(xp[4] * kc.x, xp[5] * kc.y);
                        __half2 h3v = __floats2half2_rn(xp[6] * kc.z, 0.f);
                        val = make_uint4(*(uint32_t*)&h0v, *(uint32_t*)&h1v,
                                         *(uint32_t*)&h2v, *(uint32_t*)&h3v);
                    }
                    *(uint4*)(bt + p * PITCHB + (ch * 7 + ki) * 16) = val;
                }
            }
        }
    };
    auto cpasync_A = [&](int gg) {
        const char* src = (const char*)&g_W[t][gg][0][0];
        uint32_t dst = sbase + SM_A + (gg & 1) * A_TILE;
#pragma unroll
        for (int i = 0; i < 8; i++) {
            int idx = i * 256 + tid;
            if (idx < 1920) CP16(dst + idx * 16, src + idx * 16);
        }
        CP_COMMIT();
    };
    auto stage_xk_direct = [&](int gg) {   // prologue only
        float* xs = (float*)(smem + SM_X + (gg & 1) * XBUFB);
        float* km = (float*)(smem + SM_KM + (gg & 1) * 448);
#pragma unroll
        for (int i = 0; i < 3; i++) {
            int id = tid + i * 256;
            if (id < 2 * XSTG) {
                int ch = id >= XSTG, ii = id - ch * XSTG;
                float v = (h0 * 31 + ii < 961) ? xb[(size_t)(gg * 2 + ch) * 961 + h0 * 31 + ii] : 0.f;
                xs[ch * XCH + (ii / 31) * 32 + (ii % 31)] = v;
            }
        }
        if (tid < KG) km[tid] = kern_fetch(gg);
    };

    // ---------- prologue ----------
    cpasync_A(0);
    stage_xk_direct(0);
    stage_xk_direct(1);
    __syncthreads();           // xs/km(0),(1) + rtab visible
    build_B(0);
    CP_WAIT0();                // A(0) in

    float acc[2][5][4];
#pragma unroll
    for (int mi = 0; mi < 2; mi++)
#pragma unroll
        for (int j = 0; j < 5; j++)
#pragma unroll
            for (int q = 0; q < 4; q++) acc[mi][j][q] = 0.f;

    const uint32_t apat = (uint32_t)((mw * 32 + (lid & 15)) * PITCHB + (lid >> 4) * 16);
    const uint32_t bpat = (uint32_t)((nw * 40 + (lid & 7) + ((lid & 16) ? 8 : 0)) * PITCHB
                                     + ((lid & 8) ? 16 : 0));
    const int l2 = lid & 15;
    const uint32_t bpat2 = (uint32_t)((nw * 40 + 32 + (l2 & 7)) * PITCHB + ((l2 & 8) ? 16 : 0));

    // ---------- main loop: ONE sync per group ----------
#pragma unroll 1
    for (int g = 0; g < NGROUP; g++) {
        const int buf = g & 1;
        __syncthreads();   // publishes: B(g), xs/km(g+1), A(g)

        if (g + 1 < NGROUP) cpasync_A(g + 1);

        // prefetch x(g+2)/kern(g+2) into regs
        float xv[3]; float kv = 0.f;
        if (g + 2 < NGROUP) {
#pragma unroll
            for (int i = 0; i < 3; i++) {
                int id = tid + i * 256;
                xv[i] = 0.f;
                if (id < 2 * XSTG) {
                    int ch = id >= XSTG, ii = id - ch * XSTG;
                    if (h0 * 31 + ii < 961)
                        xv[i] = xb[(size_t)((g + 2) * 2 + ch) * 961 + h0 * 31 + ii];
                }
            }
            kv = kern_fetch(g + 2);
        }

        // MMA(g)
        {
            const uint32_t ab = sbase + SM_A + buf * A_TILE + apat;
            const uint32_t bb = sbase + SM_B + buf * B_TILE;
#pragma unroll
            for (int k = 0; k < KSTEPS; k++) {
                uint32_t A0[4], A1[4], Bv[10];
                ldsm4(A0, ab + k * 32);
                ldsm4(A1, ab + 3840 + k * 32);
                ldsm4(&Bv[0], bb + bpat  + k * 32);
                ldsm4(&Bv[4], bb + bpat  + 3840 + k * 32);
                ldsm2(&Bv[8], bb + bpat2 + k * 32);
#pragma unroll
                for (int j = 0; j < 5; j++) {
                    const uint32_t* bf = &Bv[j * 2];
                    mma_f16(acc[0][j], A0, bf);
                    mma_f16(acc[1][j], A1, bf);
                }
            }
        }

        if (g + 1 < NGROUP) build_B((g + 1) & 1);

        // stage x(g+2)/km(g+2) into buf g&1
        if (g + 2 < NGROUP) {
            float* xs = (float*)(smem + SM_X + buf * XBUFB);
            float* km = (float*)(smem + SM_KM + buf * 448);
#pragma unroll
            for (int i = 0; i < 3; i++) {
                int id = tid + i * 256;
                if (id < 2 * XSTG) {
                    int ch = id >= XSTG, ii = id - ch * XSTG;
                    xs[ch * XCH + (ii / 31) * 32 + (ii % 31)] = xv[i];
                }
            }
            if (tid < KG) km[tid] = kv;
        }

        CP_WAIT0();        // A(g+1) arrived
    }

    // ---------- epilogue ----------
    const float s = 1.0f / 256.0f;
#pragma unroll
    for (int mi = 0; mi < 2; mi++) {
        int o = o0 + mw * 32 + mi * 16 + (lid >> 2);
        float bv0 = __ldg(bias + o);
        float bv1 = __ldg(bias + o + 8);
        float* r0 = out + ((size_t)b * O_ + o) * HW;
        float* r1 = r0 + 8 * HW;
#pragma unroll
        for (int j = 0; j < 5; j++) {
            int p = p0 + nw * 40 + j * 8 + 2 * (lid & 3);
            if (p < HW)     r0[p]     = acc[mi][j][0] * s + bv0;
            if (p + 1 < HW) r0[p + 1] = acc[mi][j][1] * s + bv0;
            if (p < HW)     r1[p]     = acc[mi][j][2] * s + bv1;
            if (p + 1 < HW) r1[p + 1] = acc[mi][j][3] * s + bv1;
        }
    }
}

extern "C" void kernel_launch(void* const* d_in, const int* in_sizes, int n_in,
                              void* d_out, int out_size) {
    const float* x      = (const float*)d_in[0];
    const float* kernel = (const float*)d_in[1];
    const float* weight = (const float*)d_in[2];
    const float* bias   = (const float*)d_in[3];
    float* out = (float*)d_out;

    cudaFuncSetAttribute(dwconv_hmma8, cudaFuncAttributeMaxDynamicSharedMemorySize, SMEM_DYN);

    precompute_w<<<15360, 256>>>(weight);
    dwconv_hmma8<<<512, THREADS, SMEM_DYN>>>(x, kernel, bias, out);
}